// round 1
// baseline (speedup 1.0000x reference)
#include <cuda_runtime.h>
#include <cstddef>

// Problem constants
#define BB    8
#define HH    8
#define NQ    1024
#define NKV   1024
#define DHD   64
#define DM    512
#define BHN   (BB*HH)   // 64

// ---------------- device scratch (no allocations allowed) ----------------
__device__ float g_Qh[(size_t)BHN*NQ*DHD];      // [bh][q][d]   16 MB
__device__ float g_Kh[(size_t)BHN*NKV*DHD];     // [bh][k][d]   16 MB
__device__ float g_Vh[(size_t)BHN*NKV*DHD];     // [bh][k][d]   16 MB
__device__ float g_Sb[(size_t)NQ*BHN*NKV];      // [q][bh][k]  268 MB
__device__ float g_ctx[(size_t)BB*NQ*DM];       // [b][q][h*64+d] 16 MB
__device__ float g_attn_fallback[(size_t)BHN*NQ*NKV]; // only if harness wants out-only

// =====================================================================
// Kernel 1/4: C[M,512] = A[M,512] @ W[512,512] + bias, optional permuted
// store into [B,H,N,DH] layout.  BM=BN=128, BK=8, 256 thr, 8x8 microtile.
// Grid: (512/128=4, M/128)
// =====================================================================
__global__ __launch_bounds__(256) void proj_gemm(
    const float* __restrict__ A, const float* __restrict__ W,
    const float* __restrict__ bias, float* __restrict__ C, int permute)
{
    const int K = 512, N = 512;
    __shared__ float As[8][132];
    __shared__ float Ws[8][128];
    int tid  = threadIdx.x;
    int cRow = blockIdx.y, cCol = blockIdx.x;
    int aRow = tid >> 1;            // 0..127
    int aCol = (tid & 1) << 2;      // 0 or 4
    int wRow = tid >> 5;            // 0..7
    int wCol = (tid & 31) << 2;     // 0..124
    int tRow = (tid >> 4) << 3;     // 0..120
    int tCol = (tid & 15) << 3;     // 0..120

    const float* Ap = A + (size_t)(cRow*128 + aRow)*K + aCol;
    const float* Wp = W + (size_t)wRow*N + cCol*128 + wCol;

    float acc[8][8];
#pragma unroll
    for (int i = 0; i < 8; i++)
#pragma unroll
        for (int j = 0; j < 8; j++) acc[i][j] = 0.f;

    for (int kb = 0; kb < K; kb += 8) {
        float4 a4 = *(const float4*)(Ap + kb);
        As[aCol+0][aRow] = a4.x;
        As[aCol+1][aRow] = a4.y;
        As[aCol+2][aRow] = a4.z;
        As[aCol+3][aRow] = a4.w;
        *(float4*)&Ws[wRow][wCol] = *(const float4*)(Wp + (size_t)kb*N);
        __syncthreads();
#pragma unroll
        for (int kk = 0; kk < 8; kk++) {
            float ra[8], rb[8];
            *(float4*)&ra[0] = *(float4*)&As[kk][tRow];
            *(float4*)&ra[4] = *(float4*)&As[kk][tRow+4];
            *(float4*)&rb[0] = *(float4*)&Ws[kk][tCol];
            *(float4*)&rb[4] = *(float4*)&Ws[kk][tCol+4];
#pragma unroll
            for (int i = 0; i < 8; i++)
#pragma unroll
                for (int j = 0; j < 8; j++)
                    acc[i][j] += ra[i]*rb[j];
        }
        __syncthreads();
    }

    int colBase = cCol*128 + tCol;
    float bv[8];
#pragma unroll
    for (int j = 0; j < 8; j++) bv[j] = bias[colBase + j];

#pragma unroll
    for (int i = 0; i < 8; i++) {
        int m = cRow*128 + tRow + i;
#pragma unroll
        for (int j = 0; j < 8; j++) acc[i][j] += bv[j];
        float4 lo = make_float4(acc[i][0],acc[i][1],acc[i][2],acc[i][3]);
        float4 hi = make_float4(acc[i][4],acc[i][5],acc[i][6],acc[i][7]);
        if (permute) {
            int b = m >> 10, q = m & 1023;
            int h = colBase >> 6, dd = colBase & 63;   // 8 cols stay within one head
            float* dst = C + ((size_t)(b*HH + h)*NQ + q)*DHD + dd;
            *(float4*)dst       = lo;
            *(float4*)(dst + 4) = hi;
        } else {
            float* dst = C + (size_t)m*512 + colBase;
            *(float4*)dst       = lo;
            *(float4*)(dst + 4) = hi;
        }
    }
}

// =====================================================================
// Kernel 2/4: Sbias[q][bh][k] = sum_d Qh[bh][q][d] * R[q][k][d]
// CTA: fixed q, k-tile of 128, all 64 bh.  256 thr, 4bh x 8k microtile.
// R is staged in smem once and reused by all 64 bh rows (64x reuse).
// Grid: (NKV/128=8, NQ=1024). Dyn smem: (64*64 + 64*132)*4 = 50176 B
// =====================================================================
__global__ __launch_bounds__(256) void bias_gemm(
    const float* __restrict__ Qh, const float* __restrict__ R,
    float* __restrict__ Sb)
{
    extern __shared__ float sm[];
    float* Qs = sm;            // [d][bh]  stride 64
    float* Rs = sm + 64*64;    // [d][k]   stride 132
    int tid = threadIdx.x;
    int q   = blockIdx.y;
    int k0  = blockIdx.x * 128;

    for (int idx = tid; idx < 64*16; idx += 256) {
        int bh = idx >> 4, d0 = (idx & 15) << 2;
        float4 v = *(const float4*)&Qh[((size_t)bh*NQ + q)*DHD + d0];
        Qs[(d0+0)*64 + bh] = v.x;
        Qs[(d0+1)*64 + bh] = v.y;
        Qs[(d0+2)*64 + bh] = v.z;
        Qs[(d0+3)*64 + bh] = v.w;
    }
    for (int idx = tid; idx < 128*16; idx += 256) {
        int kk = idx >> 4, d0 = (idx & 15) << 2;
        float4 v = *(const float4*)&R[((size_t)q*NKV + k0 + kk)*DHD + d0];
        Rs[(d0+0)*132 + kk] = v.x;
        Rs[(d0+1)*132 + kk] = v.y;
        Rs[(d0+2)*132 + kk] = v.z;
        Rs[(d0+3)*132 + kk] = v.w;
    }
    __syncthreads();

    int tx = tid & 15, ty = tid >> 4;
    int bh0 = ty*4, kk0 = tx*8;
    float acc[4][8];
#pragma unroll
    for (int i = 0; i < 4; i++)
#pragma unroll
        for (int j = 0; j < 8; j++) acc[i][j] = 0.f;

#pragma unroll 4
    for (int d = 0; d < 64; d++) {
        float4 a  = *(float4*)&Qs[d*64  + bh0];
        float4 r0 = *(float4*)&Rs[d*132 + kk0];
        float4 r1 = *(float4*)&Rs[d*132 + kk0 + 4];
        float av[4] = {a.x,a.y,a.z,a.w};
        float rv[8] = {r0.x,r0.y,r0.z,r0.w,r1.x,r1.y,r1.z,r1.w};
#pragma unroll
        for (int i = 0; i < 4; i++)
#pragma unroll
            for (int j = 0; j < 8; j++)
                acc[i][j] += av[i]*rv[j];
    }

#pragma unroll
    for (int i = 0; i < 4; i++) {
        float* dst = Sb + ((size_t)q*BHN + bh0 + i)*NKV + k0 + kk0;
        *(float4*)dst     = make_float4(acc[i][0],acc[i][1],acc[i][2],acc[i][3]);
        *(float4*)(dst+4) = make_float4(acc[i][4],acc[i][5],acc[i][6],acc[i][7]);
    }
}

// =====================================================================
// Kernel 3/4: fused attention.  CTA per (bh, 32-query tile). 256 thr.
//  Phase 1: S[q,k] = (Q·K^T + Sbias)*scale + maskbias, scores in smem
//  Phase 2: warp softmax per row, write attn to gmem, keep p in smem
//  Phase 3: ctx = P @ V
// Dyn smem: 32*1028 + 64*36 + 64*132 + 1024 floats = 178688 B
// Grid: (64, 32)
// =====================================================================
#define SROW 1028
__global__ __launch_bounds__(256) void attn_kernel(
    const float* __restrict__ Qh, const float* __restrict__ Kh,
    const float* __restrict__ Vh, const float* __restrict__ Sb,
    const int* __restrict__ mask, float* __restrict__ attn,
    float* __restrict__ ctx)
{
    extern __shared__ float sm[];
    float* S  = sm;                  // [32][1028]
    float* Qs = sm + 32*SROW;        // [64][36]   (d-major, q fast)
    float* Ks = Qs + 64*36;          // [64][132]  (d-major, k fast) / reused as Vs[64][68]
    float* mb = Ks + 64*132;         // [1024]
    int tid = threadIdx.x;
    int bh  = blockIdx.x;
    int q0  = blockIdx.y * 32;
    int b = bh >> 3, h = bh & 7;

    for (int idx = tid; idx < 32*16; idx += 256) {
        int qq = idx >> 4, d0 = (idx & 15) << 2;
        float4 v = *(const float4*)&Qh[((size_t)bh*NQ + q0 + qq)*DHD + d0];
        Qs[(d0+0)*36 + qq] = v.x;
        Qs[(d0+1)*36 + qq] = v.y;
        Qs[(d0+2)*36 + qq] = v.z;
        Qs[(d0+3)*36 + qq] = v.w;
    }
    for (int k = tid; k < NKV; k += 256)
        mb[k] = mask[b*NKV + k] ? 0.f : -1e30f;

    const float scale = 0.125f;     // DH^-0.5
    int tx = tid & 31, ty = tid >> 5;

    // ---- Phase 1: QK^T + bias ----
    for (int kb = 0; kb < 8; kb++) {
        __syncthreads();
        for (int idx = tid; idx < 128*16; idx += 256) {
            int kk = idx >> 4, d0 = (idx & 15) << 2;
            float4 v = *(const float4*)&Kh[((size_t)bh*NKV + kb*128 + kk)*DHD + d0];
            Ks[(d0+0)*132 + kk] = v.x;
            Ks[(d0+1)*132 + kk] = v.y;
            Ks[(d0+2)*132 + kk] = v.z;
            Ks[(d0+3)*132 + kk] = v.w;
        }
        __syncthreads();
        float acc[4][4];
#pragma unroll
        for (int i = 0; i < 4; i++)
#pragma unroll
            for (int j = 0; j < 4; j++) acc[i][j] = 0.f;
#pragma unroll 8
        for (int d = 0; d < 64; d++) {
            float4 a = *(float4*)&Qs[d*36  + ty*4];
            float4 k4 = *(float4*)&Ks[d*132 + tx*4];
            float av[4] = {a.x,a.y,a.z,a.w};
            float kv[4] = {k4.x,k4.y,k4.z,k4.w};
#pragma unroll
            for (int i = 0; i < 4; i++)
#pragma unroll
                for (int j = 0; j < 4; j++)
                    acc[i][j] += av[i]*kv[j];
        }
        int kcol = kb*128 + tx*4;
#pragma unroll
        for (int i = 0; i < 4; i++) {
            int qq = ty*4 + i;
            float4 bb = *(const float4*)&Sb[((size_t)(q0+qq)*BHN + bh)*NKV + kcol];
            float4 r;
            r.x = (acc[i][0] + bb.x)*scale + mb[kcol+0];
            r.y = (acc[i][1] + bb.y)*scale + mb[kcol+1];
            r.z = (acc[i][2] + bb.z)*scale + mb[kcol+2];
            r.w = (acc[i][3] + bb.w)*scale + mb[kcol+3];
            *(float4*)&S[qq*SROW + kcol] = r;
        }
    }
    __syncthreads();

    // ---- Phase 2: softmax (warp per 4 rows) + attn store ----
    int lane = tid & 31, wid = tid >> 5;
    for (int r = 0; r < 4; r++) {
        float* row = S + (wid*4 + r)*SROW;
        float m = -3.4e38f;
        for (int k = lane; k < NKV; k += 32) m = fmaxf(m, row[k]);
#pragma unroll
        for (int o = 16; o; o >>= 1) m = fmaxf(m, __shfl_xor_sync(0xffffffffu, m, o));
        float s = 0.f;
        for (int k = lane; k < NKV; k += 32) {
            float e = __expf(row[k] - m);
            row[k] = e; s += e;
        }
#pragma unroll
        for (int o = 16; o; o >>= 1) s += __shfl_xor_sync(0xffffffffu, s, o);
        float inv = 1.f / s;
        __syncwarp();
        float* arow = attn + ((size_t)bh*NQ + q0 + wid*4 + r)*NKV;
        for (int k = lane*4; k < NKV; k += 128) {
            float4 v = *(float4*)&row[k];
            v.x *= inv; v.y *= inv; v.z *= inv; v.w *= inv;
            *(float4*)&row[k] = v;
            *(float4*)&arow[k] = v;
        }
        __syncwarp();
    }
    __syncthreads();

    // ---- Phase 3: ctx = P @ V ----
    float* Vs = Ks;                // [64][68]
    int dgx = tid & 15, qx = tid >> 4;
    float4 c0 = make_float4(0,0,0,0), c1 = make_float4(0,0,0,0);
    for (int kb = 0; kb < 16; kb++) {
        for (int idx = tid; idx < 64*16; idx += 256) {
            int kk = idx >> 4, d0 = (idx & 15) << 2;
            *(float4*)&Vs[kk*68 + d0] =
                *(const float4*)&Vh[((size_t)bh*NKV + kb*64 + kk)*DHD + d0];
        }
        __syncthreads();
#pragma unroll 4
        for (int kk4 = 0; kk4 < 16; kk4++) {
            float4 p0 = *(float4*)&S[(qx*2+0)*SROW + kb*64 + kk4*4];
            float4 p1 = *(float4*)&S[(qx*2+1)*SROW + kb*64 + kk4*4];
            const float* vb = &Vs[(kk4*4)*68 + dgx*4];
            float4 v0 = *(const float4*)(vb);
            float4 v1 = *(const float4*)(vb + 68);
            float4 v2 = *(const float4*)(vb + 136);
            float4 v3 = *(const float4*)(vb + 204);
#define FMA4(c, s, v) c.x += (s)*(v).x; c.y += (s)*(v).y; c.z += (s)*(v).z; c.w += (s)*(v).w;
            FMA4(c0, p0.x, v0) FMA4(c0, p0.y, v1) FMA4(c0, p0.z, v2) FMA4(c0, p0.w, v3)
            FMA4(c1, p1.x, v0) FMA4(c1, p1.y, v1) FMA4(c1, p1.z, v2) FMA4(c1, p1.w, v3)
        }
        __syncthreads();
    }
    int qg = q0 + qx*2;
    float* dst = ctx + ((size_t)b*NQ + qg)*DM + h*DHD + dgx*4;
    *(float4*)dst        = c0;
    *(float4*)(dst + DM) = c1;
}

// =====================================================================
// launcher
// =====================================================================
extern "C" void kernel_launch(void* const* d_in, const int* in_sizes, int n_in,
                              void* d_out, int out_size)
{
    const float* q    = (const float*)d_in[0];
    const float* kv   = (const float*)d_in[1];
    const int*   mask = (const int*)  d_in[2];
    const float* Wq   = (const float*)d_in[3];
    const float* bq   = (const float*)d_in[4];
    const float* Wk   = (const float*)d_in[5];
    const float* bk   = (const float*)d_in[6];
    const float* Wv   = (const float*)d_in[7];
    const float* bv   = (const float*)d_in[8];
    const float* Wo   = (const float*)d_in[9];
    const float* bo   = (const float*)d_in[10];
    const float* R    = (const float*)d_in[11];

    float* out = (float*)d_out;                       // [B,NQ,512]
    const size_t out_elems  = (size_t)BB*NQ*DM;       // 4,194,304
    const size_t attn_elems = (size_t)BHN*NQ*NKV;     // 67,108,864

    float *Qh, *Kh, *Vh, *Sb, *ctx, *attn_fb;
    cudaGetSymbolAddress((void**)&Qh,  g_Qh);
    cudaGetSymbolAddress((void**)&Kh,  g_Kh);
    cudaGetSymbolAddress((void**)&Vh,  g_Vh);
    cudaGetSymbolAddress((void**)&Sb,  g_Sb);
    cudaGetSymbolAddress((void**)&ctx, g_ctx);
    cudaGetSymbolAddress((void**)&attn_fb, g_attn_fallback);

    float* attn = ((size_t)out_size >= out_elems + attn_elems)
                ? (out + out_elems) : attn_fb;

    const int biasSmem = (64*64 + 64*132) * 4;             // 50176
    const int attnSmem = (32*SROW + 64*36 + 64*132 + 1024) * 4; // 178688
    cudaFuncSetAttribute(bias_gemm, cudaFuncAttributeMaxDynamicSharedMemorySize, biasSmem);
    cudaFuncSetAttribute(attn_kernel, cudaFuncAttributeMaxDynamicSharedMemorySize, attnSmem);

    dim3 gProj(4, 64);   // (512/128, 8192/128)
    proj_gemm<<<gProj, 256>>>(q,  Wq, bq, Qh, 1);
    proj_gemm<<<gProj, 256>>>(kv, Wk, bk, Kh, 1);
    proj_gemm<<<gProj, 256>>>(kv, Wv, bv, Vh, 1);

    bias_gemm<<<dim3(8, 1024), 256, biasSmem>>>(Qh, R, Sb);

    attn_kernel<<<dim3(64, 32), 256, attnSmem>>>(Qh, Kh, Vh, Sb, mask, attn, ctx);

    proj_gemm<<<gProj, 256>>>(ctx, Wo, bo, out, 0);
}

// round 2
// speedup vs baseline: 1.1562x; 1.1562x over previous
#include <cuda_runtime.h>
#include <cstdint>
#include <cstddef>

#define BB    8
#define HH    8
#define NQ    1024
#define NKV   1024
#define DHD   64
#define DM    512
#define BHN   (BB*HH)   // 64

typedef unsigned long long ull;

// packed f32x2 FMA: c = a*b + c  (sm_103a FFMA2)
#define FMA2(c,a,b) asm("fma.rn.f32x2 %0, %1, %2, %0;" : "+l"(c) : "l"(a), "l"(b))

__device__ __forceinline__ ull dup2(float x) {
    ull r; unsigned u = __float_as_uint(x);
    asm("mov.b64 %0, {%1, %1};" : "=l"(r) : "r"(u));
    return r;
}
__device__ __forceinline__ float2 unpk(ull v) {
    unsigned lo, hi;
    asm("mov.b64 {%0, %1}, %2;" : "=r"(lo), "=r"(hi) : "l"(v));
    return make_float2(__uint_as_float(lo), __uint_as_float(hi));
}

// ---------------- device scratch ----------------
__device__ float g_Qh[(size_t)BHN*NQ*DHD];
__device__ float g_Kh[(size_t)BHN*NKV*DHD];
__device__ float g_Vh[(size_t)BHN*NKV*DHD];
__device__ float g_Sb[(size_t)NQ*BHN*NKV];
__device__ float g_ctx[(size_t)BB*NQ*DM];
__device__ float g_attn_fallback[(size_t)BHN*NQ*NKV];

// =====================================================================
// Kernel 1/4: C[M,512] = A[M,512] @ W[512,512] + bias (f32x2 core)
// 128x128 tile, BK=8, 256 thr, 8 rows x 8 cols per thread (cols split
// as {nc*4..+3} and {64+nc*4..+3} for conflict-free LDS).
// =====================================================================
__global__ __launch_bounds__(256) void proj_gemm(
    const float* __restrict__ A, const float* __restrict__ W,
    const float* __restrict__ bias, float* __restrict__ C, int permute)
{
    const int K = 512, N = 512;
    __shared__ float As2[8][260];   // a-rows duplicated: [k][2*row]
    __shared__ float Ws[8][128];
    int tid  = threadIdx.x;
    int cRow = blockIdx.y, cCol = blockIdx.x;
    int aRow = tid >> 1;            // 0..127
    int aCol = (tid & 1) << 2;      // 0 or 4
    int wRow = tid >> 5;            // 0..7
    int wCol = (tid & 31) << 2;     // 0..124
    int tRow = (tid >> 4) << 3;     // 0..120
    int nc   = tid & 15;            // 0..15

    const float* Ap = A + (size_t)(cRow*128 + aRow)*K + aCol;
    const float* Wp = W + (size_t)wRow*N + cCol*128 + wCol;

    ull acc[8][4];
#pragma unroll
    for (int i = 0; i < 8; i++)
#pragma unroll
        for (int j = 0; j < 4; j++) acc[i][j] = 0ULL;

    for (int kb = 0; kb < K; kb += 8) {
        float4 a4 = *(const float4*)(Ap + kb);
        As2[aCol+0][aRow*2] = a4.x; As2[aCol+0][aRow*2+1] = a4.x;
        As2[aCol+1][aRow*2] = a4.y; As2[aCol+1][aRow*2+1] = a4.y;
        As2[aCol+2][aRow*2] = a4.z; As2[aCol+2][aRow*2+1] = a4.z;
        As2[aCol+3][aRow*2] = a4.w; As2[aCol+3][aRow*2+1] = a4.w;
        *(float4*)&Ws[wRow][wCol] = *(const float4*)(Wp + (size_t)kb*N);
        __syncthreads();
#pragma unroll
        for (int kk = 0; kk < 8; kk++) {
            ulonglong2 A0 = *(const ulonglong2*)&As2[kk][tRow*2];
            ulonglong2 A1 = *(const ulonglong2*)&As2[kk][tRow*2 + 4];
            ulonglong2 A2 = *(const ulonglong2*)&As2[kk][tRow*2 + 8];
            ulonglong2 A3 = *(const ulonglong2*)&As2[kk][tRow*2 + 12];
            ulonglong2 B0 = *(const ulonglong2*)&Ws[kk][nc*4];
            ulonglong2 B1 = *(const ulonglong2*)&Ws[kk][64 + nc*4];
            ull av[8] = {A0.x, A0.y, A1.x, A1.y, A2.x, A2.y, A3.x, A3.y};
#pragma unroll
            for (int i = 0; i < 8; i++) {
                FMA2(acc[i][0], av[i], B0.x);
                FMA2(acc[i][1], av[i], B0.y);
                FMA2(acc[i][2], av[i], B1.x);
                FMA2(acc[i][3], av[i], B1.y);
            }
        }
        __syncthreads();
    }

    int colA = cCol*128 + nc*4;
    int colB = colA + 64;
    float4 bA = *(const float4*)&bias[colA];
    float4 bB = *(const float4*)&bias[colB];

#pragma unroll
    for (int i = 0; i < 8; i++) {
        int m = cRow*128 + tRow + i;
        float2 p0 = unpk(acc[i][0]), p1 = unpk(acc[i][1]);
        float2 p2 = unpk(acc[i][2]), p3 = unpk(acc[i][3]);
        float4 vA = make_float4(p0.x + bA.x, p0.y + bA.y, p1.x + bA.z, p1.y + bA.w);
        float4 vB = make_float4(p2.x + bB.x, p2.y + bB.y, p3.x + bB.z, p3.y + bB.w);
        if (permute) {
            int b = m >> 10, q = m & 1023;
            int hA = colA >> 6, dA = colA & 63;
            int hB = colB >> 6, dB = colB & 63;
            *(float4*)(C + ((size_t)(b*HH + hA)*NQ + q)*DHD + dA) = vA;
            *(float4*)(C + ((size_t)(b*HH + hB)*NQ + q)*DHD + dB) = vB;
        } else {
            *(float4*)(C + (size_t)m*512 + colA) = vA;
            *(float4*)(C + (size_t)m*512 + colB) = vB;
        }
    }
}

// =====================================================================
// Kernel 2/4: Sbias[q][bh][k] = sum_d Qh[bh][q][d] * R[q][k][d]
// CTA: fixed q, k-tile 256, all 64 bh. 256 thr, 8bh x 8k per thread.
// Q duplicated in smem for f32x2 broadcast. Grid: (4, 1024).
// =====================================================================
__global__ __launch_bounds__(256, 2) void bias_gemm(
    const float* __restrict__ Qh, const float* __restrict__ R,
    float* __restrict__ Sb)
{
    extern __shared__ float sm[];
    float* Qs2 = sm;             // [d=64][132]  (64 bh duplicated + pad)
    float* Rs  = sm + 64*132;    // [d=64][260]  (256 k + pad)
    int tid = threadIdx.x;
    int q   = blockIdx.y;
    int k0  = blockIdx.x * 256;
    int kg  = tid & 31, bhg = tid >> 5;

    for (int idx = tid; idx < 64*16; idx += 256) {
        int bh = idx >> 4, d0 = (idx & 15) << 2;
        float4 v = *(const float4*)&Qh[((size_t)bh*NQ + q)*DHD + d0];
        Qs2[(d0+0)*132 + 2*bh] = v.x; Qs2[(d0+0)*132 + 2*bh+1] = v.x;
        Qs2[(d0+1)*132 + 2*bh] = v.y; Qs2[(d0+1)*132 + 2*bh+1] = v.y;
        Qs2[(d0+2)*132 + 2*bh] = v.z; Qs2[(d0+2)*132 + 2*bh+1] = v.z;
        Qs2[(d0+3)*132 + 2*bh] = v.w; Qs2[(d0+3)*132 + 2*bh+1] = v.w;
    }
    for (int idx = tid; idx < 256*16; idx += 256) {
        int kk = idx >> 4, d0 = (idx & 15) << 2;
        float4 v = *(const float4*)&R[((size_t)q*NKV + k0 + kk)*DHD + d0];
        Rs[(d0+0)*260 + kk] = v.x;
        Rs[(d0+1)*260 + kk] = v.y;
        Rs[(d0+2)*260 + kk] = v.z;
        Rs[(d0+3)*260 + kk] = v.w;
    }
    __syncthreads();

    ull acc[8][4];
#pragma unroll
    for (int i = 0; i < 8; i++)
#pragma unroll
        for (int j = 0; j < 4; j++) acc[i][j] = 0ULL;

#pragma unroll 2
    for (int d = 0; d < 64; d++) {
        ulonglong2 A0 = *(const ulonglong2*)&Qs2[d*132 + bhg*16];
        ulonglong2 A1 = *(const ulonglong2*)&Qs2[d*132 + bhg*16 + 4];
        ulonglong2 A2 = *(const ulonglong2*)&Qs2[d*132 + bhg*16 + 8];
        ulonglong2 A3 = *(const ulonglong2*)&Qs2[d*132 + bhg*16 + 12];
        ulonglong2 R0 = *(const ulonglong2*)&Rs[d*260 + kg*4];
        ulonglong2 R1 = *(const ulonglong2*)&Rs[d*260 + 128 + kg*4];
        ull av[8] = {A0.x, A0.y, A1.x, A1.y, A2.x, A2.y, A3.x, A3.y};
#pragma unroll
        for (int i = 0; i < 8; i++) {
            FMA2(acc[i][0], av[i], R0.x);
            FMA2(acc[i][1], av[i], R0.y);
            FMA2(acc[i][2], av[i], R1.x);
            FMA2(acc[i][3], av[i], R1.y);
        }
    }

#pragma unroll
    for (int i = 0; i < 8; i++) {
        int bh = bhg*8 + i;
        float* dst = Sb + ((size_t)q*BHN + bh)*NKV + k0;
        float2 p0 = unpk(acc[i][0]), p1 = unpk(acc[i][1]);
        float2 p2 = unpk(acc[i][2]), p3 = unpk(acc[i][3]);
        *(float4*)(dst + kg*4)       = make_float4(p0.x, p0.y, p1.x, p1.y);
        *(float4*)(dst + 128 + kg*4) = make_float4(p2.x, p2.y, p3.x, p3.y);
    }
}

// =====================================================================
// Kernel 3/4: fused attention. CTA per (bh, 32-q tile). 256 thr.
// Phase1: QK^T in k-chunks of 256, 4q x 8k per thread, f32x2.
// Phase2: warp softmax + attn store.
// Phase3: P@V with k-split across thread halves, f32x2 along d.
// =====================================================================
#define SROW 1028
#define QS2_OFF (32*SROW)                 // 32896
#define KS_OFF  (QS2_OFF + 64*72)         // 37504
#define MB_OFF  (KS_OFF + 64*260)         // 54144
#define ATTN_SMEM ((MB_OFF + 1024)*4)     // 220672 bytes

__global__ __launch_bounds__(256) void attn_kernel(
    const float* __restrict__ Qh, const float* __restrict__ Kh,
    const float* __restrict__ Vh, const float* __restrict__ Sb,
    const int* __restrict__ mask, float* __restrict__ attn,
    float* __restrict__ ctx)
{
    extern __shared__ float sm[];
    float* S   = sm;
    float* Qs2 = sm + QS2_OFF;   // [d=64][72] : 32 q duplicated + pad
    float* Ks  = sm + KS_OFF;    // [d=64][260]: 256 k chunk + pad
    float* mb  = sm + MB_OFF;    // [1024]
    int tid = threadIdx.x;
    int bh  = blockIdx.x;
    int q0  = blockIdx.y * 32;
    int b = bh >> 3, h = bh & 7;

    for (int idx = tid; idx < 32*16; idx += 256) {
        int qq = idx >> 4, d0 = (idx & 15) << 2;
        float4 v = *(const float4*)&Qh[((size_t)bh*NQ + q0 + qq)*DHD + d0];
        Qs2[(d0+0)*72 + 2*qq] = v.x; Qs2[(d0+0)*72 + 2*qq+1] = v.x;
        Qs2[(d0+1)*72 + 2*qq] = v.y; Qs2[(d0+1)*72 + 2*qq+1] = v.y;
        Qs2[(d0+2)*72 + 2*qq] = v.z; Qs2[(d0+2)*72 + 2*qq+1] = v.z;
        Qs2[(d0+3)*72 + 2*qq] = v.w; Qs2[(d0+3)*72 + 2*qq+1] = v.w;
    }
    for (int k = tid; k < NKV; k += 256)
        mb[k] = mask[b*NKV + k] ? 0.f : -1e30f;

    const float scale = 0.125f;
    int kg = tid & 31, qg = tid >> 5;   // qg = warp id -> Q reads broadcast

    // ---- Phase 1: QK^T + bias, 4 chunks of 256 k ----
    for (int c = 0; c < 4; c++) {
        __syncthreads();
        for (int idx = tid; idx < 256*16; idx += 256) {
            int kk = idx >> 4, d0 = (idx & 15) << 2;
            float4 v = *(const float4*)&Kh[((size_t)bh*NKV + c*256 + kk)*DHD + d0];
            Ks[(d0+0)*260 + kk] = v.x;
            Ks[(d0+1)*260 + kk] = v.y;
            Ks[(d0+2)*260 + kk] = v.z;
            Ks[(d0+3)*260 + kk] = v.w;
        }
        __syncthreads();

        ull acc[4][4];
#pragma unroll
        for (int i = 0; i < 4; i++)
#pragma unroll
            for (int j = 0; j < 4; j++) acc[i][j] = 0ULL;

#pragma unroll 4
        for (int d = 0; d < 64; d++) {
            ulonglong2 QA = *(const ulonglong2*)&Qs2[d*72 + qg*8];
            ulonglong2 QB = *(const ulonglong2*)&Qs2[d*72 + qg*8 + 4];
            ulonglong2 K0 = *(const ulonglong2*)&Ks[d*260 + kg*4];
            ulonglong2 K1 = *(const ulonglong2*)&Ks[d*260 + 128 + kg*4];
            ull av[4] = {QA.x, QA.y, QB.x, QB.y};
#pragma unroll
            for (int i = 0; i < 4; i++) {
                FMA2(acc[i][0], av[i], K0.x);
                FMA2(acc[i][1], av[i], K0.y);
                FMA2(acc[i][2], av[i], K1.x);
                FMA2(acc[i][3], av[i], K1.y);
            }
        }

        int cb = c*256;
#pragma unroll
        for (int i = 0; i < 4; i++) {
            int qq = qg*4 + i;
            const float* sbrow = Sb + ((size_t)(q0+qq)*BHN + bh)*NKV + cb;
            float4 b0 = *(const float4*)(sbrow + kg*4);
            float4 b1 = *(const float4*)(sbrow + 128 + kg*4);
            float4 m0 = *(const float4*)&mb[cb + kg*4];
            float4 m1 = *(const float4*)&mb[cb + 128 + kg*4];
            float2 p0 = unpk(acc[i][0]), p1 = unpk(acc[i][1]);
            float2 p2 = unpk(acc[i][2]), p3 = unpk(acc[i][3]);
            float4 r0, r1;
            r0.x = (p0.x + b0.x)*scale + m0.x;
            r0.y = (p0.y + b0.y)*scale + m0.y;
            r0.z = (p1.x + b0.z)*scale + m0.z;
            r0.w = (p1.y + b0.w)*scale + m0.w;
            r1.x = (p2.x + b1.x)*scale + m1.x;
            r1.y = (p2.y + b1.y)*scale + m1.y;
            r1.z = (p3.x + b1.z)*scale + m1.z;
            r1.w = (p3.y + b1.w)*scale + m1.w;
            *(float4*)&S[qq*SROW + cb + kg*4]       = r0;
            *(float4*)&S[qq*SROW + cb + 128 + kg*4] = r1;
        }
    }
    __syncthreads();

    // ---- Phase 2: softmax + attn store ----
    int lane = tid & 31, wid = tid >> 5;
    for (int r = 0; r < 4; r++) {
        float* row = S + (wid*4 + r)*SROW;
        float m = -3.4e38f;
        for (int k = lane; k < NKV; k += 32) m = fmaxf(m, row[k]);
#pragma unroll
        for (int o = 16; o; o >>= 1) m = fmaxf(m, __shfl_xor_sync(0xffffffffu, m, o));
        float s = 0.f;
        for (int k = lane; k < NKV; k += 32) {
            float e = __expf(row[k] - m);
            row[k] = e; s += e;
        }
#pragma unroll
        for (int o = 16; o; o >>= 1) s += __shfl_xor_sync(0xffffffffu, s, o);
        float inv = 1.f / s;
        __syncwarp();
        float* arow = attn + ((size_t)bh*NQ + q0 + wid*4 + r)*NKV;
        for (int k = lane*4; k < NKV; k += 128) {
            float4 v = *(float4*)&row[k];
            v.x *= inv; v.y *= inv; v.z *= inv; v.w *= inv;
            *(float4*)&row[k] = v;
            *(float4*)&arow[k] = v;
        }
        __syncwarp();
    }
    __syncthreads();

    // ---- Phase 3: ctx = P @ V, k-split in half ----
    int half = tid >> 7;          // 0: k[0..511], 1: k[512..1023]
    int t    = tid & 127;
    int qg2  = t >> 4;            // 8 groups x 4 q
    int dg   = t & 15;            // 16 groups x 4 d
    float* Vs = Ks + half * (64*68);    // [64][68] per half

    ull acc[4][2];
#pragma unroll
    for (int i = 0; i < 4; i++) { acc[i][0] = 0ULL; acc[i][1] = 0ULL; }

    for (int kb = 0; kb < 8; kb++) {
        int koff = half*512 + kb*64;
        for (int r = 0; r < 8; r++) {
            int idx = t + r*128;
            int kk = idx >> 4, d0 = (idx & 15) << 2;
            *(float4*)&Vs[kk*68 + d0] =
                *(const float4*)&Vh[((size_t)bh*NKV + koff + kk)*DHD + d0];
        }
        __syncthreads();
#pragma unroll 2
        for (int kk4 = 0; kk4 < 16; kk4++) {
            float4 p[4];
#pragma unroll
            for (int i = 0; i < 4; i++)
                p[i] = *(float4*)&S[(qg2*4 + i)*SROW + koff + kk4*4];
#pragma unroll
            for (int tt = 0; tt < 3+1; tt++) {
                ulonglong2 v = *(const ulonglong2*)&Vs[(kk4*4 + tt)*68 + dg*4];
                float pv[4] = { tt==0?p[0].x: tt==1?p[0].y: tt==2?p[0].z:p[0].w,
                                tt==0?p[1].x: tt==1?p[1].y: tt==2?p[1].z:p[1].w,
                                tt==0?p[2].x: tt==1?p[2].y: tt==2?p[2].z:p[2].w,
                                tt==0?p[3].x: tt==1?p[3].y: tt==2?p[3].z:p[3].w };
#pragma unroll
                for (int i = 0; i < 4; i++) {
                    ull pd = dup2(pv[i]);
                    FMA2(acc[i][0], pd, v.x);
                    FMA2(acc[i][1], pd, v.y);
                }
            }
        }
        __syncthreads();
    }

    float* scr = Qs2;   // reuse as 32x64 scratch
    if (half == 1) {
#pragma unroll
        for (int i = 0; i < 4; i++) {
            float2 a = unpk(acc[i][0]), c2 = unpk(acc[i][1]);
            *(float4*)&scr[(qg2*4 + i)*64 + dg*4] = make_float4(a.x, a.y, c2.x, c2.y);
        }
    }
    __syncthreads();
    if (half == 0) {
#pragma unroll
        for (int i = 0; i < 4; i++) {
            int qq = qg2*4 + i;
            float4 o = *(float4*)&scr[qq*64 + dg*4];
            float2 a = unpk(acc[i][0]), c2 = unpk(acc[i][1]);
            o.x += a.x; o.y += a.y; o.z += c2.x; o.w += c2.y;
            *(float4*)(ctx + ((size_t)b*NQ + q0 + qq)*DM + h*DHD + dg*4) = o;
        }
    }
}

// =====================================================================
// launcher
// =====================================================================
extern "C" void kernel_launch(void* const* d_in, const int* in_sizes, int n_in,
                              void* d_out, int out_size)
{
    const float* q    = (const float*)d_in[0];
    const float* kv   = (const float*)d_in[1];
    const int*   mask = (const int*)  d_in[2];
    const float* Wq   = (const float*)d_in[3];
    const float* bq   = (const float*)d_in[4];
    const float* Wk   = (const float*)d_in[5];
    const float* bk   = (const float*)d_in[6];
    const float* Wv   = (const float*)d_in[7];
    const float* bv   = (const float*)d_in[8];
    const float* Wo   = (const float*)d_in[9];
    const float* bo   = (const float*)d_in[10];
    const float* R    = (const float*)d_in[11];

    float* out = (float*)d_out;
    const size_t out_elems  = (size_t)BB*NQ*DM;
    const size_t attn_elems = (size_t)BHN*NQ*NKV;

    float *Qh, *Kh, *Vh, *Sb, *ctx, *attn_fb;
    cudaGetSymbolAddress((void**)&Qh,  g_Qh);
    cudaGetSymbolAddress((void**)&Kh,  g_Kh);
    cudaGetSymbolAddress((void**)&Vh,  g_Vh);
    cudaGetSymbolAddress((void**)&Sb,  g_Sb);
    cudaGetSymbolAddress((void**)&ctx, g_ctx);
    cudaGetSymbolAddress((void**)&attn_fb, g_attn_fallback);

    float* attn = ((size_t)out_size >= out_elems + attn_elems)
                ? (out + out_elems) : attn_fb;

    const int biasSmem = (64*132 + 64*260) * 4;   // 100352
    cudaFuncSetAttribute(bias_gemm, cudaFuncAttributeMaxDynamicSharedMemorySize, biasSmem);
    cudaFuncSetAttribute(attn_kernel, cudaFuncAttributeMaxDynamicSharedMemorySize, ATTN_SMEM);

    dim3 gProj(4, 64);
    proj_gemm<<<gProj, 256>>>(q,  Wq, bq, Qh, 1);
    proj_gemm<<<gProj, 256>>>(kv, Wk, bk, Kh, 1);
    proj_gemm<<<gProj, 256>>>(kv, Wv, bv, Vh, 1);

    bias_gemm<<<dim3(4, 1024), 256, biasSmem>>>(Qh, R, Sb);

    attn_kernel<<<dim3(64, 32), 256, ATTN_SMEM>>>(Qh, Kh, Vh, Sb, mask, attn, ctx);

    proj_gemm<<<gProj, 256>>>(ctx, Wo, bo, out, 0);
}